// round 17
// baseline (speedup 1.0000x reference)
#include <cuda_runtime.h>
#include <cuda_fp16.h>
#include <cstdint>
#include <math.h>

// ConvergedInhibition == circular deconvolution along C=128 channels.
// Y = G @ X, G[r][j] = g[(r-j)&127], g = ifft(1/fft(delta-k)).
// R17: R16 + (a) 2-kstep ldsm.x4 packing on 8-col warp slices (halves
//      ldsm wavefronts at SAME instruction density; identity col layout,
//      float2 epilogue) + (b) atomic work-stealing tile scheduler
//      (absorbs remainder + inter-SM spread). In-kernel prep, depth-2
//      cp.async, fused convert, 512 threads, <=64 regs, 2 CTAs/SM.

#define CCH     128
#define HWSZ    4096
#define NBATCH  64
#define SCOPE   27
#define NTILE_N 64
#define NTHREADS 512
#define NTILES_TOTAL (NBATCH * (HWSZ / NTILE_N))   // 4096

#define SPITCH_B 272                    // staging row: 64 fp32 + 16B pad
#define STAGE_B  (CCH * SPITCH_B)       // 34816
#define XPITCH_B 272                    // fp16 row: 128 fp16 + 16B pad
#define F16_B    (NTILE_N * XPITCH_B)   // 17408
#define SMEM_S0  0
#define SMEM_S1  STAGE_B
#define SMEM_F0  (2 * STAGE_B)          // 69632
#define SMEM_F1  (2 * STAGE_B + F16_B)  // 87040
#define SMEM_DYN (2 * STAGE_B + 2 * F16_B)  // 104448

__device__ int g_ctr;                   // work-stealing tile counter

// ---------------------------------------------------------------------------
__device__ __forceinline__ uint32_t s2u(const void* p) {
    uint32_t a;
    asm("{ .reg .u64 t; cvta.to.shared.u64 t, %1; cvt.u32.u64 %0, t; }"
        : "=r"(a) : "l"(p));
    return a;
}
__device__ __forceinline__ uint32_t pack_f16x2(float lo, float hi) {
    uint32_t r;
    asm("cvt.rn.f16x2.f32 %0, %1, %2;" : "=r"(r) : "f"(hi), "f"(lo));
    return r;
}
__device__ __forceinline__ void cp_async16(uint32_t dst, const void* src) {
    asm volatile("cp.async.cg.shared.global [%0], [%1], 16;"
                 :: "r"(dst), "l"(src) : "memory");
}
__device__ __forceinline__ void cp_commit() {
    asm volatile("cp.async.commit_group;" ::: "memory");
}
__device__ __forceinline__ void cp_wait0() {
    asm volatile("cp.async.wait_group 0;" ::: "memory");
}
__device__ __forceinline__ void cp_wait1() {
    asm volatile("cp.async.wait_group 1;" ::: "memory");
}
__device__ __forceinline__ void ldsm_x4(uint32_t& r0, uint32_t& r1,
                                        uint32_t& r2, uint32_t& r3, uint32_t a) {
    asm volatile("ldmatrix.sync.aligned.m8n8.x4.shared.b16 {%0,%1,%2,%3}, [%4];"
                 : "=r"(r0), "=r"(r1), "=r"(r2), "=r"(r3) : "r"(a));
}
__device__ __forceinline__ void mma16816(float* c, uint32_t ax, uint32_t ay,
                                         uint32_t az, uint32_t b0, uint32_t b1) {
    asm volatile(
        "mma.sync.aligned.m16n8k16.row.col.f32.f16.f16.f32 "
        "{%0,%1,%2,%3}, {%4,%5,%6,%4}, {%7,%8}, {%0,%1,%2,%3};"
        : "+f"(c[0]), "+f"(c[1]), "+f"(c[2]), "+f"(c[3])
        : "r"(ax), "r"(ay), "r"(az), "r"(b0), "r"(b1));
}

// ---------------------------------------------------------------------------
// Persistent staged GEMM, 512 threads, in-kernel prep, fused convert,
// work-stealing. Tile = 128m x 64n. 16 warps: warp_m = wid&1 (64 rows),
// warp_n = wid>>1 (8 cols).
// ---------------------------------------------------------------------------
__global__ void __launch_bounds__(NTHREADS, 2)
gemm_mma(const float* __restrict__ x, const float* __restrict__ filt,
         float* __restrict__ y) {
    extern __shared__ char smc[];
    __shared__ float tw_re[CCH], tw_im[CCH];
    __shared__ float inv_re[CCH], inv_im[CCH];
    __shared__ float ft[SCOPE];
    __shared__ float g_s[CCH];
    __shared__ int s_grab;

    const int tid  = threadIdx.x;
    const int wid  = tid >> 5;
    const int lane = tid & 31;
    const int warp_m = wid & 1;
    const int warp_n = wid >> 1;

    const uint32_t smb = s2u(smc);

#define STAGE_TILE(tt, sb)                                                   \
    do {                                                                     \
        const float* xb_ = x + (size_t)((tt) >> 6) * CCH * HWSZ              \
                             + ((tt) & 63) * NTILE_N;                        \
        _Pragma("unroll")                                                    \
        for (int i_ = 0; i_ < 4; i_++) {                                     \
            int c_ = tid + NTHREADS * i_;                                    \
            int k_ = c_ >> 4, n4_ = c_ & 15;                                 \
            cp_async16((sb) + k_ * SPITCH_B + n4_ * 16,                      \
                       xb_ + (size_t)k_ * HWSZ + n4_ * 4);                   \
        }                                                                    \
    } while (0)

    // ---- grab first three tiles (work stealing) ----
    __shared__ int s_t0, s_t1, s_t2;
    if (tid == 0) {
        s_t0 = atomicAdd(&g_ctr, 1);
        s_t1 = atomicAdd(&g_ctr, 1);
        s_t2 = atomicAdd(&g_ctr, 1);
    }
    __syncthreads();
    int cur = s_t0, nxt = s_t1, nx2 = s_t2;
    if (cur >= NTILES_TOTAL) return;

    // ---- stage tile0 FIRST: its DRAM latency covers the g computation ----
    STAGE_TILE(cur, smb + SMEM_S0);
    cp_commit();                       // group: cur

    // ---- in-CTA prep: g = real(ifft(1/fft(delta - k_rolled))) ----
    if (tid < SCOPE) ft[tid] = filt[tid];
    if (tid < CCH) {
        float s, c;
        sincosf(6.283185307179586f * (float)tid / 128.0f, &s, &c);
        tw_re[tid] = c; tw_im[tid] = s;
    }
    __syncthreads();
    if (tid < CCH) {
        float fr = 1.0f, fi = 0.0f;
#pragma unroll
        for (int j = 0; j < SCOPE; j++) {
            int p = (115 + j) & 127;
            int idx = (tid * p) & 127;
            fr -= ft[j] * tw_re[idx];
            fi += ft[j] * tw_im[idx];
        }
        float d = fr * fr + fi * fi;
        inv_re[tid] = fr / d; inv_im[tid] = -fi / d;
    }
    __syncthreads();
    if (tid < CCH) {
        float acc = 0.0f;
        for (int f = 0; f < CCH; f++) {
            int idx = (f * tid) & 127;
            acc += tw_re[idx] * inv_re[f] - tw_im[idx] * inv_im[f];
        }
        g_s[tid] = acc * (1.0f / 128.0f);
    }
    __syncthreads();

    // ---- A fragments: 8 diagonal classes, 3 words (w == x) ----
    // warp covers 64 rows (4 mtiles); class = (warp_m*4 + mt - ks)&7.
    uint32_t ax[8], ay[8], az[8];
#pragma unroll
    for (int i = 0; i < 8; i++) {
        int cls = ((warp_m * 4) + i) & 7;
        int d0 = (16 * cls + (lane >> 2) - 2 * (lane & 3)) & 127;
        ax[i] = pack_f16x2(g_s[d0], g_s[(d0 - 1) & 127]);
        int d1 = (d0 + 8) & 127;
        ay[i] = pack_f16x2(g_s[d1], g_s[(d1 - 1) & 127]);
        int d2 = (d0 - 8) & 127;
        az[i] = pack_f16x2(g_s[d2], g_s[(d2 - 1) & 127]);
    }

    // convert constants: thread -> (n-row n0, k-eighth kq); identity cols
    const int n0 = tid & 63;
    const int kq = tid >> 6;                 // 0..7 (16 k's each)

    // ldsm constants: matrices = warp's 8 n-rows at k-offsets +0,+16,+32,+48
    // (2 ksteps per ldsm.x4: (b0,b1) kstep 2j, (b2,b3) kstep 2j+1)
    const uint32_t lm_off = (lane & 7) * XPITCH_B + ((lane >> 3) & 3) * 16
                          + (uint32_t)warp_n * 8 * XPITCH_B;

#define CONVERT_CHUNK(ch, sk_, dk_)                                          \
    do {                                                                     \
        float v_[8];                                                         \
        _Pragma("unroll")                                                    \
        for (int ii_ = 0; ii_ < 8; ii_++)                                    \
            v_[ii_] = *reinterpret_cast<const float*>(                       \
                (sk_) + (size_t)((ch) * 8 + ii_) * SPITCH_B);                \
        uint4 hq_;                                                           \
        hq_.x = pack_f16x2(v_[0], v_[1]);                                    \
        hq_.y = pack_f16x2(v_[2], v_[3]);                                    \
        hq_.z = pack_f16x2(v_[4], v_[5]);                                    \
        hq_.w = pack_f16x2(v_[6], v_[7]);                                    \
        *reinterpret_cast<uint4*>((dk_) + (ch) * 16) = hq_;                  \
    } while (0)

    // ---- prologue: convert tile0 (serial), stage tile1 ----
    cp_wait0();
    __syncthreads();
    {
        const char* sk = smc + SMEM_S0 + n0 * 4 + (size_t)(kq * 16) * SPITCH_B;
        char* dk = smc + SMEM_F0 + (uint32_t)n0 * XPITCH_B + kq * 32;
        CONVERT_CHUNK(0, sk, dk);
        CONVERT_CHUNK(1, sk, dk);
    }
    __syncthreads();                   // stg0 reads done; f16[0] visible
    if (nxt < NTILES_TOTAL) STAGE_TILE(nxt, smb + SMEM_S1);
    cp_commit();                       // group: nxt

    int par = 0;
    // invariant at loop top: f16[par] = cur (visible); stg[par^1] = cp(nxt)
    // committed; stg[par] free; nx2 = tile to stage now.
    for (; cur < NTILES_TOTAL; ) {
        // 1. issue cp(nx2) into the free staging buffer stg[par]
        if (nx2 < NTILES_TOTAL)
            STAGE_TILE(nx2, smb + (par ? SMEM_S1 : SMEM_S0));
        cp_commit();

        // 2. cp(nxt) landed (covered by previous iteration's work)
        cp_wait1();
        __syncthreads();

        // 3. fused: mma(cur) from f16[par] + convert(nxt) -> f16[par^1]
        const bool hn = nxt < NTILES_TOTAL;
        {
            const char* csk = smc + (par ? SMEM_S0 : SMEM_S1) + n0 * 4
                            + (size_t)(kq * 16) * SPITCH_B;
            char* cdk = smc + (par ? SMEM_F0 : SMEM_F1)
                      + (uint32_t)n0 * XPITCH_B + kq * 32;
            const uint32_t xh_base = smb + (par ? SMEM_F1 : SMEM_F0) + lm_off;

            float acc[4][4];
#pragma unroll
            for (int mt = 0; mt < 4; mt++)
#pragma unroll
                for (int r = 0; r < 4; r++) acc[mt][r] = 0.0f;

#pragma unroll
            for (int ks2 = 0; ks2 < 4; ks2++) {
                uint32_t b0, b1, b2, b3;
                ldsm_x4(b0, b1, b2, b3, xh_base + (uint32_t)ks2 * 64);
#pragma unroll
                for (int kk = 0; kk < 2; kk++) {
                    const int ks = 2 * ks2 + kk;
                    const uint32_t e0 = kk ? b2 : b0;
                    const uint32_t e1 = kk ? b3 : b1;
#pragma unroll
                    for (int mt = 0; mt < 4; mt++) {
                        const int ai = (mt - ks) & 7;
                        mma16816(acc[mt], ax[ai], ay[ai], az[ai], e0, e1);
                    }
                }
                if (ks2 == 1 && hn) CONVERT_CHUNK(0, csk, cdk);
                if (ks2 == 3 && hn) CONVERT_CHUNK(1, csk, cdk);
            }

            // epilogue: lane holds cols (2q, 2q+1) of rows m0, m0+8
            float* yb = y + (size_t)(cur >> 6) * CCH * HWSZ
                          + (cur & 63) * NTILE_N + warp_n * 8
                          + 2 * (lane & 3);
#pragma unroll
            for (int mt = 0; mt < 4; mt++) {
                int m0 = warp_m * 64 + mt * 16 + (lane >> 2);
                *reinterpret_cast<float2*>(yb + (size_t)m0 * HWSZ) =
                    make_float2(acc[mt][0], acc[mt][1]);
                *reinterpret_cast<float2*>(yb + (size_t)(m0 + 8) * HWSZ) =
                    make_float2(acc[mt][2], acc[mt][3]);
            }
        }

        // grab the next prefetch target before the closing barrier
        if (tid == 0)
            s_grab = (nx2 < NTILES_TOTAL) ? atomicAdd(&g_ctr, 1)
                                          : NTILES_TOTAL;
        // 4. f16[par^1] complete for all; stg[par^1] reads done; s_grab valid
        __syncthreads();

        cur = nxt; nxt = nx2; nx2 = s_grab;
        par ^= 1;
    }
#undef STAGE_TILE
#undef CONVERT_CHUNK
}

// ---------------------------------------------------------------------------
extern "C" void kernel_launch(void* const* d_in, const int* in_sizes, int n_in,
                              void* d_out, int out_size) {
    const float* act  = (const float*)d_in[0];
    const float* filt = (const float*)d_in[1];
    if (n_in >= 2 && in_sizes[0] == SCOPE) {
        act  = (const float*)d_in[1];
        filt = (const float*)d_in[0];
    }
    float* out = (float*)d_out;

    void* ctr_ptr = nullptr;
    cudaGetSymbolAddress(&ctr_ptr, g_ctr);
    cudaMemsetAsync(ctr_ptr, 0, sizeof(int));

    int nsm = 148;
    cudaDeviceGetAttribute(&nsm, cudaDevAttrMultiProcessorCount, 0);
    int grid = 2 * nsm;
    if (grid > NTILES_TOTAL) grid = NTILES_TOTAL;

    cudaFuncSetAttribute(gemm_mma,
                         cudaFuncAttributeMaxDynamicSharedMemorySize, SMEM_DYN);
    gemm_mma<<<grid, NTHREADS, SMEM_DYN>>>(act, filt, out);
}